// round 14
// baseline (speedup 1.0000x reference)
#include <cuda_runtime.h>

// Bilateral filter, B=2 C=3 H=W=384, ksize=9, sigma=1.7.
// Density exp ~ minimax linear poly in u=(v-c)^2 on [0,1]; filter = separable
// 9-tap Gaussian moments M1,M2,M3:
//   den = b1*M2 + (-2*b1*c)*M1 + (b0+b1*c^2)*S2
//   num = b1*M3 + (-2*b1*c)*M2 + (b0+b1*c^2)*M1
// Scalar FFMA body (weights fold to FFMA-imm, rt=1) + 512-thread CTAs for
// occupancy: grid is CTA-limited (432/148 = 2.92/SM), so warps/CTA is the
// only occupancy lever. Vertical pass: exactly 1 output row per thread.

#define TW   64
#define TH   32
#define HALO 4
#define SWX  72
#define SWXP 76          // raw row stride in floats (304B, 16B-aligned)
#define SWY  40
#define KS   9
#define NT   512

// exp(-A*d*d), A = 1/(2*1.7^2)
#define G0f 1.00000000f
#define G1f 0.84112888f
#define G2f 0.50055313f
#define G3f 0.21074770f
#define G4f 0.06277701f
#define S2f 17.8963970f
// minimax linear for exp(-A*u), u in [0,1]
#define B0f 0.99828148f
#define B1f (-0.15887112f)

__global__ __launch_bounds__(NT, 3)
void bilateral9_kernel(const float* __restrict__ x, float* __restrict__ out,
                       int H, int W) {
    __shared__ __align__(16) float raw[SWY][SWXP];   // 12.2 KB
    __shared__ __align__(16) float pM1[SWY][TW];     // 10 KB
    __shared__ __align__(16) float pM2[SWY][TW];     // 10 KB
    __shared__ __align__(16) float pM3[SWY][TW];     // 10 KB

    const int plane = blockIdx.z;
    const float* xp = x + (size_t)plane * H * W;
    float* op = out + (size_t)plane * H * W;
    const int x0 = blockIdx.x * TW;
    const int y0 = blockIdx.y * TH;
    const int tid = threadIdx.x;

    // ---- load 72x40 raw tile ----
    const bool interior = (x0 >= HALO) && (x0 + TW + HALO <= W) &&
                          (y0 >= HALO) && (y0 + TH + HALO <= H);
    if (interior) {
        const float* src = xp + (size_t)(y0 - HALO) * W + (x0 - HALO);
        #pragma unroll
        for (int k = 0; k < 2; k++) {
            int idx = tid + k * NT;                  // 720 float4 = 2880 floats
            if (idx < 720) {
                int ly = idx / 18;
                int lx = idx - ly * 18;
                float4 v = *(const float4*)(src + (size_t)ly * W + lx * 4);
                *(float4*)&raw[ly][lx * 4] = v;
            }
        }
    } else {
        #pragma unroll
        for (int k = 0; k < 6; k++) {
            int idx = tid + k * NT;
            if (idx < 2880) {
                int ly = idx / SWX;
                int lx = idx - ly * SWX;
                int gy = y0 + ly - HALO;
                int gx = x0 + lx - HALO;
                gy = gy < 0 ? -gy : (gy >= H ? 2 * H - 2 - gy : gy);
                gx = gx < 0 ? -gx : (gx >= W ? 2 * W - 2 - gx : gx);
                raw[ly][lx] = xp[(size_t)gy * W + gx];
            }
        }
    }
    __syncthreads();

    const float G[5] = { G0f, G1f, G2f, G3f, G4f };

    // ---- horizontal pass: 40 rows x 32 col-pairs = 1280 units ----
    // 512 threads: rows rid, rid+16, and (rid<8) rid+32. Tap powers v^2,v^3
    // shared between the 2 adjacent output columns of a unit.
    {
        const int cp  = tid & 31;        // cols 2cp, 2cp+1
        const int rid = tid >> 5;        // 0..15
        #pragma unroll
        for (int rr = 0; rr < 3; rr++) {
            const int r = rid + rr * 16;
            if (rr < 2 || rid < 8) {     // rows 0..39
                const float* rp = &raw[r][2 * cp];
                float f[10], f2[10], f3[10];
                #pragma unroll
                for (int i = 0; i < 5; i++) {
                    float2 L = *(const float2*)(rp + 2 * i);
                    f[2 * i] = L.x;
                    f[2 * i + 1] = L.y;
                }
                #pragma unroll
                for (int i = 0; i < 10; i++) {
                    f2[i] = f[i] * f[i];
                    f3[i] = f2[i] * f[i];
                }

                float a1A, a2A, a3A, a1B, a2B, a3B;
                a1A = G4f * f[0];  a2A = G4f * f2[0];  a3A = G4f * f3[0];
                a1B = G4f * f[1];  a2B = G4f * f2[1];  a3B = G4f * f3[1];
                #pragma unroll
                for (int j = 1; j < KS; j++) {
                    const float w = G[j < 4 ? 4 - j : j - 4];
                    a1A = fmaf(w, f[j],      a1A);
                    a2A = fmaf(w, f2[j],     a2A);
                    a3A = fmaf(w, f3[j],     a3A);
                    a1B = fmaf(w, f[j + 1],  a1B);
                    a2B = fmaf(w, f2[j + 1], a2B);
                    a3B = fmaf(w, f3[j + 1], a3B);
                }

                *(float2*)&pM1[r][2 * cp] = make_float2(a1A, a1B);
                *(float2*)&pM2[r][2 * cp] = make_float2(a2A, a2B);
                *(float2*)&pM3[r][2 * cp] = make_float2(a3A, a3B);
            }
        }
    }
    __syncthreads();

    // ---- vertical pass: 1 output row per thread, float4 column quads ----
    const int cg  = tid & 15;            // col quad -> cols 4cg..4cg+3
    const int row = tid >> 4;            // 0..31 (output row within tile)

    float4 m1 = make_float4(0.f, 0.f, 0.f, 0.f);
    float4 m2 = make_float4(0.f, 0.f, 0.f, 0.f);
    float4 m3 = make_float4(0.f, 0.f, 0.f, 0.f);

    #pragma unroll
    for (int t = 0; t < KS; t++) {       // window rows row .. row+8
        const float w = G[t < 4 ? 4 - t : t - 4];
        float4 h1 = *(const float4*)&pM1[row + t][4 * cg];
        float4 h2 = *(const float4*)&pM2[row + t][4 * cg];
        float4 h3 = *(const float4*)&pM3[row + t][4 * cg];
        m1.x = fmaf(w, h1.x, m1.x);
        m1.y = fmaf(w, h1.y, m1.y);
        m1.z = fmaf(w, h1.z, m1.z);
        m1.w = fmaf(w, h1.w, m1.w);
        m2.x = fmaf(w, h2.x, m2.x);
        m2.y = fmaf(w, h2.y, m2.y);
        m2.z = fmaf(w, h2.z, m2.z);
        m2.w = fmaf(w, h2.w, m2.w);
        m3.x = fmaf(w, h3.x, m3.x);
        m3.y = fmaf(w, h3.y, m3.y);
        m3.z = fmaf(w, h3.z, m3.z);
        m3.w = fmaf(w, h3.w, m3.w);
    }

    // ---- epilogue: 4 cols ----
    {
        float4 cc = *(const float4*)&raw[row + HALO][4 * cg + HALO];
        const float* cv = &cc.x;
        const float* M1 = &m1.x;
        const float* M2 = &m2.x;
        const float* M3 = &m3.x;
        float4 o;
        float* ov = &o.x;
        #pragma unroll
        for (int i = 0; i < 4; i++) {
            float c  = cv[i];
            float c2 = c * c;
            float p1 = (-2.0f * B1f) * c;          // -2*b1*c
            float q  = fmaf(B1f, c2, B0f);         // b0 + b1*c^2
            float den = fmaf(q, S2f, fmaf(p1, M1[i], B1f * M2[i]));
            float num = fmaf(q, M1[i], fmaf(p1, M2[i], B1f * M3[i]));
            ov[i] = __fdividef(num, den);
        }
        int oy = y0 + row;
        *(float4*)&op[(size_t)oy * W + x0 + 4 * cg] = o;
    }
}

extern "C" void kernel_launch(void* const* d_in, const int* in_sizes, int n_in,
                              void* d_out, int out_size) {
    const float* x = (const float*)d_in[0];
    float* out = (float*)d_out;
    const int H = 384, W = 384;
    const int planes = out_size / (H * W);   // B*C = 6

    cudaFuncSetAttribute(bilateral9_kernel,
                         cudaFuncAttributePreferredSharedMemoryCarveout, 100);

    dim3 block(NT, 1, 1);
    dim3 grid(W / TW, H / TH, planes);
    bilateral9_kernel<<<grid, block>>>(x, out, H, W);
}